// round 8
// baseline (speedup 1.0000x reference)
#include <cuda_runtime.h>
#include <cstdint>

// Problem constants
#define S_LEN  4096
#define D_SZ   100
#define TD     200
#define NROWS  8192
#define NC     6
#define CO     52

// K2 tiling
#define NDP     128                  // d padded to 128 (f32x2 pairs)
#define MB      16                   // rows per tile
#define NTILES  (NROWS / MB)         // 512
#define VS      224                  // v_s row stride
#define KC      20
#define NCHUNKS 1110                 // 1100 symmetric + 10 Ww chunks
#define PADK    (NCHUNKS * KC)       // 22200
#define CHELEMS (KC * NDP)           // 2560
#define NPROD   146                  // producer blocks; block NPROD is the consumer
#define NTHR    800                  // 25 warps; consumer uses 2 threads per gate

typedef unsigned long long u64;

// ---------------- device scratch ----------------
__device__ float g_V0T[(size_t)PADK * NDP];     // 11.4 MB packed symmetric V0 (+Ww tail)
__device__ int   g_ck[NCHUNKS];
__device__ float g_xg[(size_t)NROWS * 400];
__device__ float g_h3[(size_t)NROWS * CO];
__device__ float g_h [(size_t)NROWS * D_SZ];
__device__ int   g_L_dev[1];
__device__ int   g_flag[NTILES];
__device__ int   g_ctr[1];

// ---------------- helpers ----------------
__device__ __forceinline__ float sigf(float x) {
    return __fdividef(1.0f, 1.0f + __expf(-x));
}
__device__ __forceinline__ float tanhfast(float x) {
    return fmaf(2.0f, sigf(2.0f * x), -1.0f);
}
__device__ __forceinline__ void fma2(u64& acc, u64 a, u64 b) {
    asm volatile("fma.rn.f32x2 %0, %1, %2, %0;" : "+l"(acc) : "l"(a), "l"(b));
}
__device__ __forceinline__ u64 add2(u64 a, u64 b) {
    u64 r;
    asm("add.rn.f32x2 %0, %1, %2;" : "=l"(r) : "l"(a), "l"(b));
    return r;
}
__device__ __forceinline__ u64 dup2(float x) {
    u64 r;
    asm("mov.b64 %0, {%1, %1};" : "=l"(r) : "f"(x));
    return r;
}
__device__ __forceinline__ float2 unpack2(u64 v) {
    float2 r;
    asm("mov.b64 {%0, %1}, %2;" : "=f"(r.x), "=f"(r.y) : "l"(v));
    return r;
}
// volatile shared loads: pinned ordering vs the volatile fma2's so ptxas
// cannot hoist the whole h vector into 50 live registers (spill protection).
// NOTE: v2.u64 form requires the address to be 16-byte aligned.
__device__ __forceinline__ void lds_v2u64(u64& x, u64& y, uint32_t addr) {
    asm volatile("ld.shared.v2.u64 {%0, %1}, [%2];" : "=l"(x), "=l"(y) : "r"(addr));
}
__device__ __forceinline__ void lds_u64(u64& x, uint32_t addr) {
    asm volatile("ld.shared.u64 %0, [%1];" : "=l"(x) : "r"(addr));
}

// ---------------- K_init: chunk metadata ----------------
__global__ void k_init() {
    if (threadIdx.x == 0 && blockIdx.x == 0) {
        int c = 0;
        for (int i = 0; i < TD; i++) {
            int nch = (TD - i + KC - 1) / KC;
            for (int cc = 0; cc < nch; cc++) g_ck[c++] = (i << 16) | (i + cc * KC);
        }
        for (int cc = 0; cc < 10; cc++) g_ck[c++] = (TD << 16) | (cc * KC);
    }
}

// ---------------- K0: build packed symmetric V0T (+ Ww tail) ----------------
__global__ void k0_fill(const float* __restrict__ V, const float* __restrict__ Ww) {
    const size_t total = (size_t)PADK * NDP;
    for (size_t idx = (size_t)blockIdx.x * blockDim.x + threadIdx.x; idx < total;
         idx += (size_t)gridDim.x * blockDim.x) {
        int row = (int)(idx / NDP);
        int d   = (int)(idx % NDP);
        float val = 0.0f;
        if (d < D_SZ) {
            int ch = row / KC;
            int meta = g_ck[ch];
            int i = meta >> 16;
            int j = (meta & 0xffff) + (row - ch * KC);
            if (i < TD) {
                if (j < TD) {
                    val = V[(size_t)d * 40000 + i * TD + j];
                    if (j > i) val += V[(size_t)d * 40000 + j * TD + i];
                }
            } else {
                val = Ww[d * TD + j];
            }
        }
        g_V0T[idx] = val;
    }
}

// ---------------- K1: lengths + reset flags/counter ----------------
__global__ void k1_len(const float* __restrict__ mask, int n) {
    __shared__ float red[1024];
    float s = 0.f;
    for (int i = threadIdx.x; i < n; i += 1024) s += mask[i];
    red[threadIdx.x] = s;
    __syncthreads();
    for (int st = 512; st > 0; st >>= 1) {
        if (threadIdx.x < st) red[threadIdx.x] += red[threadIdx.x + st];
        __syncthreads();
    }
    if (threadIdx.x == 0) {
        g_L_dev[0] = (int)(red[0] + 0.5f);
        g_ctr[0] = 0;
    }
    for (int i = threadIdx.x; i < NTILES; i += 1024) g_flag[i] = 0;
}

// ============================================================================
// Fused persistent kernel: blocks 0..NPROD-1 = producers; block NPROD = LSTM
// consumer. 147 blocks co-resident (<=148 SMs) -> safe under ncu serialization.
// ============================================================================
__global__ void __launch_bounds__(NTHR, 1) k23_fused(
    const float* __restrict__ U,
    const float* __restrict__ Wb,
    const float* __restrict__ Wih, const float* __restrict__ bih, const float* __restrict__ bhh,
    const float* __restrict__ convw, const float* __restrict__ convb,
    const float* __restrict__ Whh)
{
    const int tid = threadIdx.x;
    extern __shared__ float sm[];

    if (blockIdx.x < NPROD) {
        // ======================= PRODUCER =======================
        float* v_s = sm;                               // MB*VS = 3584 floats
        float* B_s = sm + MB * VS;                     // 2*CHELEMS = 5120 floats
        float* p_s = B_s + 2 * CHELEMS;                // MB*100 = 1600 floats
        int*  s_ck = (int*)(p_s + MB * D_SZ);          // 1110 ints
        __shared__ int s_tile;

        const int tx = tid & 15;        // (tid<128) d group: 8 floats = 2 ulonglong2
        const int ty = tid >> 4;        // (tid<128) 0..7 -> 2 rows each
        const int r0 = ty * 2;
        const int d0 = tx * 8;
        const bool ldr = tid < CHELEMS / 4;   // 640 staging threads

        const int L = g_L_dev[0];

        for (int u = tid; u < NCHUNKS; u += NTHR) s_ck[u] = g_ck[u];
        __syncthreads();

        while (true) {
            if (tid == 0) s_tile = atomicAdd(g_ctr, 1);
            __syncthreads();
            const int tile = s_tile;
            __syncthreads();
            if (tile >= NTILES) break;
            const int row0 = tile * MB;

            // ---- load v (concat(prev, cur)) for 16 rows ----
            for (int e = tid; e < MB * VS; e += NTHR) {
                int rl = e / VS;
                int j  = e % VS;
                float val = 0.0f;
                if (j < TD) {
                    int row = row0 + rl;
                    int t = row & (S_LEN - 1);
                    bool bwd = row >= S_LEN;
                    int sbase = (j < D_SZ) ? (t == 0 ? 0 : t - 1) : t;
                    int col   = (j < D_SZ) ? j : j - D_SZ;
                    if (!bwd) {
                        val = U[(size_t)sbase * D_SZ + col];
                    } else if (sbase < L) {
                        int src = L - 1 - sbase;
                        src = src < 0 ? 0 : (src > S_LEN - 1 ? S_LEN - 1 : src);
                        val = U[(size_t)src * D_SZ + col];
                    }
                }
                v_s[e] = val;
            }

            // ---- prefetch chunk 0 (640 float4, 1 per staging thread) ----
            float4 pre;
            if (ldr) pre = ((const float4*)g_V0T)[tid];
            if (ldr) ((float4*)B_s)[tid] = pre;
            __syncthreads();

            u64 acc00 = 0, acc01 = 0, acc02 = 0, acc03 = 0;
            u64 acc10 = 0, acc11 = 0, acc12 = 0, acc13 = 0;

            for (int c = 0; c < NCHUNKS; c++) {
                const float* Bc = B_s + (c & 1) * CHELEMS;

                if (c + 1 < NCHUNKS && ldr)
                    pre = ((const float4*)(g_V0T + (size_t)(c + 1) * CHELEMS))[tid];

                if (tid < 128) {
                    const int meta = s_ck[c];
                    const int i  = meta >> 16;
                    const int j0 = meta & 0xffff;

                    const float vi0 = (i < TD) ? v_s[r0 * VS + i] : 1.0f;
                    const float vi1 = (i < TD) ? v_s[(r0 + 1) * VS + i] : 1.0f;
                    // k-row of B = NDP=128 floats = 32 ulonglong2; thread covers
                    // 8 floats (2 ulonglong2) at float offset d0 = tx*8.
                    const ulonglong2* bp = (const ulonglong2*)Bc + tx * 2;

#pragma unroll
                    for (int kk = 0; kk < KC; kk++) {
                        float vj0 = v_s[r0 * VS + j0 + kk];
                        float vj1 = v_s[(r0 + 1) * VS + j0 + kk];
                        u64 a0 = dup2(vi0 * vj0);
                        u64 a1 = dup2(vi1 * vj1);
                        ulonglong2 b01 = bp[kk * 32];
                        ulonglong2 b23 = bp[kk * 32 + 1];
                        fma2(acc00, a0, b01.x); fma2(acc01, a0, b01.y);
                        fma2(acc02, a0, b23.x); fma2(acc03, a0, b23.y);
                        fma2(acc10, a1, b01.x); fma2(acc11, a1, b01.y);
                        fma2(acc12, a1, b23.x); fma2(acc13, a1, b23.y);
                    }
                }

                if (c + 1 < NCHUNKS && ldr)
                    ((float4*)(B_s + ((c + 1) & 1) * CHELEMS))[tid] = pre;
                __syncthreads();
            }

            // ---- p = sigmoid(acc + Wb) ----
            if (tid < 128) {
                u64 accs[2][4] = {{acc00, acc01, acc02, acc03}, {acc10, acc11, acc12, acc13}};
#pragma unroll
                for (int rr = 0; rr < 2; rr++) {
#pragma unroll
                    for (int q = 0; q < 4; q++) {
                        float2 v2 = unpack2(accs[rr][q]);
                        int d = d0 + 2 * q;
                        if (d < D_SZ)     p_s[(r0 + rr) * D_SZ + d]     = sigf(v2.x + Wb[d]);
                        if (d + 1 < D_SZ) p_s[(r0 + rr) * D_SZ + d + 1] = sigf(v2.y + Wb[d + 1]);
                    }
                }
            }
            __syncthreads();

            // ---- x_gates = p @ Wih^T + b_ih + b_hh ----
            for (int o = tid; o < MB * 400; o += NTHR) {
                int rl = o / 400;
                int g  = o % 400;
                float a = bih[g] + bhh[g];
                const float4* wr4 = (const float4*)(Wih + (size_t)g * D_SZ);
                const float4* pr4 = (const float4*)(p_s + rl * D_SZ);
#pragma unroll 5
                for (int q = 0; q < 25; q++) {
                    float4 w = wr4[q];
                    float4 p = pr4[q];
                    a = fmaf(w.x, p.x, a);
                    a = fmaf(w.y, p.y, a);
                    a = fmaf(w.z, p.z, a);
                    a = fmaf(w.w, p.w, a);
                }
                g_xg[(size_t)(row0 + rl) * 400 + g] = a;
            }

            // ---- h3 = conv1d(p) ----
            float cw0 = convw[0], cw1 = convw[1], cw2 = convw[2], cw3 = convw[3], cw4 = convw[4];
            float cb = convb[0];
            for (int o = tid; o < MB * CO; o += NTHR) {
                int rl = o / CO;
                int oc = o % CO;
                const float* pr = p_s + rl * D_SZ;
                float s = cb;
                int base = 2 * oc - 4;
#pragma unroll
                for (int k = 0; k < 5; k++) {
                    int ix = base + k;
                    if (ix >= 0 && ix < D_SZ) {
                        float w = (k == 0) ? cw0 : (k == 1) ? cw1 : (k == 2) ? cw2 : (k == 3) ? cw3 : cw4;
                        s = fmaf(w, pr[ix], s);
                    }
                }
                g_h3[(size_t)(row0 + rl) * CO + oc] = s;
            }

            // ---- publish tile ----
            __syncthreads();
            __threadfence();
            if (tid == 0) atomicExch(&g_flag[tile], 1);
            __syncthreads();
        }
    } else {
        // ============ CONSUMER (LSTM, 2 threads per gate) ============
        // h layout in smem is PADDED so each half is 16B-aligned for LDS.128:
        //   half0: h[0..49]  at float offsets [0, 50)    (byte 0)
        //   half1: h[50..99] at float offsets [52, 102)  (byte 208 = 13*16)
        float* xg_s   = sm;                      // MB*400 = 6400 floats (25.6 KB)
        float* h_sc   = sm + MB * 400;           // 104 floats (padded halves)
        float* act_sc = h_sc + 104;              // 400 floats

        const int gate = tid >> 1;               // 0..399
        const int half = tid & 1;                // 0: h[0:50), 1: h[50:100)

        // 25 u64 weights per thread (50 regs) — fits the 80-reg budget, no spill.
        u64 w2[25];
        {
            const u64* wp = (const u64*)(Whh + (size_t)gate * D_SZ + half * 50);
#pragma unroll
            for (int j = 0; j < 25; j++) w2[j] = wp[j];
        }
        const uint32_t h_base = (uint32_t)__cvta_generic_to_shared(h_sc) + half * 208;
        const bool is_tanh = (gate >= 200 && gate < 300);

        float c = 0.0f;
        if (tid < 104) h_sc[tid] = 0.0f;
        __syncthreads();

        for (int tile = 0; tile < NTILES; tile++) {
            if (tid == 0) {
                while (atomicAdd(&g_flag[tile], 0) == 0) __nanosleep(64);
                __threadfence();
            }
            __syncthreads();

            // stage this tile's x_gates into smem (6400 floats = 1600 float4)
            {
                const float4* src = (const float4*)(g_xg + (size_t)tile * MB * 400);
                float4* dst = (float4*)xg_s;
                for (int u = tid; u < MB * 100; u += NTHR) dst[u] = src[u];
            }
            __syncthreads();

            for (int tt = 0; tt < MB; tt++) {
                const int t = tile * MB + tt;

                // half-dot over 50 h values: 6 batches of 4 u64 + 1 tail
                u64 a0 = 0ull, a1 = 0ull, a2 = 0ull, a3 = 0ull;
                uint32_t addr = h_base;
#pragma unroll
                for (int b = 0; b < 6; b++) {
                    u64 h0, h1, h2, h3;
                    lds_v2u64(h0, h1, addr);          // 16B-aligned
                    lds_v2u64(h2, h3, addr + 16);     // 16B-aligned
                    fma2(a0, w2[4 * b],     h0);
                    fma2(a1, w2[4 * b + 1], h1);
                    fma2(a2, w2[4 * b + 2], h2);
                    fma2(a3, w2[4 * b + 3], h3);
                    addr += 32;
                }
                {
                    u64 ht;
                    lds_u64(ht, addr);                // 8B tail
                    fma2(a0, w2[24], ht);
                }
                u64 st = add2(add2(a0, a1), add2(a2, a3));
                float2 uu = unpack2(st);
                float xh = uu.x + uu.y;
                xh += __shfl_xor_sync(0xffffffffu, xh, 1);
                float x = xh + xg_s[tt * 400 + gate];

                float act = is_tanh ? tanhfast(x) : sigf(x);
                if (half == 0) act_sc[gate] = act;
                __syncthreads();

                if (tid < D_SZ) {
                    float ig = act_sc[tid];
                    float fg = act_sc[100 + tid];
                    float gg = act_sc[200 + tid];
                    float og = act_sc[300 + tid];
                    c = fmaf(fg, c, ig * gg);
                    float h = og * tanhfast(c);
                    int pos = tid + (tid >= 50 ? 2 : 0);   // padded half layout
                    h_sc[pos] = h;
                    g_h[(size_t)t * D_SZ + tid] = h;
                }
                __syncthreads();
            }
        }
    }
}

// ---------------- K4: logits + log_softmax ----------------
__global__ void k4_epilogue(const float* __restrict__ Wsw, const float* __restrict__ Wsb,
                            float* __restrict__ out) {
    int t = blockIdx.x * blockDim.x + threadIdx.x;
    if (t >= S_LEN) return;
    const int L = g_L_dev[0];

    float acc[NC];
#pragma unroll
    for (int cc = 0; cc < NC; cc++) acc[cc] = Wsb[cc];

    const float* hf  = g_h  + (size_t)t * D_SZ;
    const float* h3f = g_h3 + (size_t)t * CO;

    for (int j = 0; j < D_SZ; j++) {
        float x = hf[j];
#pragma unroll
        for (int cc = 0; cc < NC; cc++) acc[cc] = fmaf(Wsw[cc * 304 + j], x, acc[cc]);
    }
    for (int j = 0; j < CO; j++) {
        float x = h3f[j];
#pragma unroll
        for (int cc = 0; cc < NC; cc++) acc[cc] = fmaf(Wsw[cc * 304 + 100 + j], x, acc[cc]);
    }

    if (t < L) {
        int sidx = L - 1 - t;
        sidx = sidx < 0 ? 0 : (sidx > S_LEN - 1 ? S_LEN - 1 : sidx);
        const float* hb  = g_h  + (size_t)(S_LEN + sidx) * D_SZ;
        const float* h3b = g_h3 + (size_t)(S_LEN + sidx) * CO;
        for (int j = 0; j < D_SZ; j++) {
            float x = hb[j];
#pragma unroll
            for (int cc = 0; cc < NC; cc++) acc[cc] = fmaf(Wsw[cc * 304 + 152 + j], x, acc[cc]);
        }
        for (int j = 0; j < CO; j++) {
            float x = h3b[j];
#pragma unroll
            for (int cc = 0; cc < NC; cc++) acc[cc] = fmaf(Wsw[cc * 304 + 252 + j], x, acc[cc]);
        }
    }

    float m = acc[0];
#pragma unroll
    for (int cc = 1; cc < NC; cc++) m = fmaxf(m, acc[cc]);
    float s = 0.0f;
#pragma unroll
    for (int cc = 0; cc < NC; cc++) s += __expf(acc[cc] - m);
    float lse = m + logf(s);
#pragma unroll
    for (int cc = 0; cc < NC; cc++) out[(size_t)t * NC + cc] = acc[cc] - lse;
}

// ---------------- launcher (single stream, fully serial-safe) ----------------
extern "C" void kernel_launch(void* const* d_in, const int* in_sizes, int n_in,
                              void* d_out, int out_size) {
    const float* U     = (const float*)d_in[0];
    const float* mask  = (const float*)d_in[1];
    const float* V     = (const float*)d_in[2];
    const float* Ww    = (const float*)d_in[3];
    const float* Wb    = (const float*)d_in[4];
    const float* Wsw   = (const float*)d_in[5];
    const float* Wsb   = (const float*)d_in[6];
    const float* Wih   = (const float*)d_in[7];
    const float* Whh   = (const float*)d_in[8];
    const float* bih   = (const float*)d_in[9];
    const float* bhh   = (const float*)d_in[10];
    const float* convw = (const float*)d_in[11];
    const float* convb = (const float*)d_in[12];
    float* out = (float*)d_out;

    const int smem2 = (MB * VS + 2 * CHELEMS + MB * D_SZ) * (int)sizeof(float)
                    + NCHUNKS * (int)sizeof(int);   // ~45.7 KB (covers consumer's 27.7 KB too)

    static bool attr_set = false;
    if (!attr_set) {
        cudaFuncSetAttribute(k23_fused, cudaFuncAttributeMaxDynamicSharedMemorySize, smem2);
        attr_set = true;
    }

    k_init<<<1, 32>>>();
    k0_fill<<<2048, 256>>>(V, Ww);
    k1_len<<<1, 1024>>>(mask, in_sizes[1]);
    k23_fused<<<NPROD + 1, NTHR, smem2>>>(U, Wb, Wih, bih, bhh, convw, convb, Whh);
    k4_epilogue<<<32, 128>>>(Wsw, Wsb, out);
}

// round 9
// speedup vs baseline: 1.0018x; 1.0018x over previous
#include <cuda_runtime.h>
#include <cstdint>

// Problem constants
#define S_LEN  4096
#define D_SZ   100
#define TD     200
#define NROWS  8192
#define NC     6
#define CO     52

// K2 tiling
#define NDP     128                  // d padded to 128 (f32x2 pairs)
#define MB      16                   // rows per tile
#define NTILES  (NROWS / MB)         // 512
#define VS      224                  // v_s row stride
#define KC      20
#define NCHUNKS 1110                 // 1100 symmetric + 10 Ww chunks
#define PADK    (NCHUNKS * KC)       // 22200
#define CHELEMS (KC * NDP)           // 2560
#define NPROD   146                  // producer blocks; block NPROD is the consumer
#define NTHR    800                  // 25 warps

typedef unsigned long long u64;

// ---------------- device scratch ----------------
__device__ float g_V0T[(size_t)PADK * NDP];     // 11.4 MB packed symmetric V0 (+Ww tail)
__device__ int   g_ck[NCHUNKS];
__device__ float g_xg[(size_t)NROWS * 400];
__device__ float g_h3[(size_t)NROWS * CO];
__device__ float g_h [(size_t)NROWS * D_SZ];
__device__ int   g_L_dev[1];
__device__ int   g_flag[NTILES];
__device__ int   g_ctr[1];

// ---------------- helpers ----------------
__device__ __forceinline__ float sigf(float x) {
    return __fdividef(1.0f, 1.0f + __expf(-x));
}
__device__ __forceinline__ float tanhfast(float x) {
    return fmaf(2.0f, sigf(2.0f * x), -1.0f);
}
__device__ __forceinline__ void fma2(u64& acc, u64 a, u64 b) {
    asm volatile("fma.rn.f32x2 %0, %1, %2, %0;" : "+l"(acc) : "l"(a), "l"(b));
}
__device__ __forceinline__ u64 add2(u64 a, u64 b) {
    u64 r;
    asm("add.rn.f32x2 %0, %1, %2;" : "=l"(r) : "l"(a), "l"(b));
    return r;
}
__device__ __forceinline__ u64 dup2(float x) {
    u64 r;
    asm("mov.b64 %0, {%1, %1};" : "=l"(r) : "f"(x));
    return r;
}
__device__ __forceinline__ float2 unpack2(u64 v) {
    float2 r;
    asm("mov.b64 {%0, %1}, %2;" : "=f"(r.x), "=f"(r.y) : "l"(v));
    return r;
}
// volatile shared loads (16B-aligned v2 form).
__device__ __forceinline__ void lds_v2u64(u64& x, u64& y, uint32_t addr) {
    asm volatile("ld.shared.v2.u64 {%0, %1}, [%2];" : "=l"(x), "=l"(y) : "r"(addr));
}
__device__ __forceinline__ void lds_u64(u64& x, uint32_t addr) {
    asm volatile("ld.shared.u64 %0, [%1];" : "=l"(x) : "r"(addr));
}

// ---------------- K_init: chunk metadata ----------------
__global__ void k_init() {
    if (threadIdx.x == 0 && blockIdx.x == 0) {
        int c = 0;
        for (int i = 0; i < TD; i++) {
            int nch = (TD - i + KC - 1) / KC;
            for (int cc = 0; cc < nch; cc++) g_ck[c++] = (i << 16) | (i + cc * KC);
        }
        for (int cc = 0; cc < 10; cc++) g_ck[c++] = (TD << 16) | (cc * KC);
    }
}

// ---------------- K0: build packed symmetric V0T (+ Ww tail) ----------------
__global__ void k0_fill(const float* __restrict__ V, const float* __restrict__ Ww) {
    const size_t total = (size_t)PADK * NDP;
    for (size_t idx = (size_t)blockIdx.x * blockDim.x + threadIdx.x; idx < total;
         idx += (size_t)gridDim.x * blockDim.x) {
        int row = (int)(idx / NDP);
        int d   = (int)(idx % NDP);
        float val = 0.0f;
        if (d < D_SZ) {
            int ch = row / KC;
            int meta = g_ck[ch];
            int i = meta >> 16;
            int j = (meta & 0xffff) + (row - ch * KC);
            if (i < TD) {
                if (j < TD) {
                    val = V[(size_t)d * 40000 + i * TD + j];
                    if (j > i) val += V[(size_t)d * 40000 + j * TD + i];
                }
            } else {
                val = Ww[d * TD + j];
            }
        }
        g_V0T[idx] = val;
    }
}

// ---------------- K1: lengths + reset flags/counter ----------------
__global__ void k1_len(const float* __restrict__ mask, int n) {
    __shared__ float red[1024];
    float s = 0.f;
    for (int i = threadIdx.x; i < n; i += 1024) s += mask[i];
    red[threadIdx.x] = s;
    __syncthreads();
    for (int st = 512; st > 0; st >>= 1) {
        if (threadIdx.x < st) red[threadIdx.x] += red[threadIdx.x + st];
        __syncthreads();
    }
    if (threadIdx.x == 0) {
        g_L_dev[0] = (int)(red[0] + 0.5f);
        g_ctr[0] = 0;
    }
    for (int i = threadIdx.x; i < NTILES; i += 1024) g_flag[i] = 0;
}

// ============================================================================
// Fused persistent kernel: blocks 0..NPROD-1 = producers; block NPROD = LSTM
// consumer. 147 blocks co-resident (<=148 SMs) -> safe under ncu serialization.
// ============================================================================
__global__ void __launch_bounds__(NTHR, 1) k23_fused(
    const float* __restrict__ U,
    const float* __restrict__ Wb,
    const float* __restrict__ Wih, const float* __restrict__ bih, const float* __restrict__ bhh,
    const float* __restrict__ convw, const float* __restrict__ convb,
    const float* __restrict__ Whh)
{
    const int tid = threadIdx.x;
    extern __shared__ float sm[];

    if (blockIdx.x < NPROD) {
        // ======================= PRODUCER (identical to validated R8) =======================
        float* v_s = sm;                               // MB*VS = 3584 floats
        float* B_s = sm + MB * VS;                     // 2*CHELEMS = 5120 floats
        float* p_s = B_s + 2 * CHELEMS;                // MB*100 = 1600 floats
        int*  s_ck = (int*)(p_s + MB * D_SZ);          // 1110 ints
        __shared__ int s_tile;

        const int tx = tid & 15;
        const int ty = tid >> 4;
        const int r0 = ty * 2;
        const int d0 = tx * 8;
        const bool ldr = tid < CHELEMS / 4;   // 640 staging threads

        const int L = g_L_dev[0];

        for (int u = tid; u < NCHUNKS; u += NTHR) s_ck[u] = g_ck[u];
        __syncthreads();

        while (true) {
            if (tid == 0) s_tile = atomicAdd(g_ctr, 1);
            __syncthreads();
            const int tile = s_tile;
            __syncthreads();
            if (tile >= NTILES) break;
            const int row0 = tile * MB;

            for (int e = tid; e < MB * VS; e += NTHR) {
                int rl = e / VS;
                int j  = e % VS;
                float val = 0.0f;
                if (j < TD) {
                    int row = row0 + rl;
                    int t = row & (S_LEN - 1);
                    bool bwd = row >= S_LEN;
                    int sbase = (j < D_SZ) ? (t == 0 ? 0 : t - 1) : t;
                    int col   = (j < D_SZ) ? j : j - D_SZ;
                    if (!bwd) {
                        val = U[(size_t)sbase * D_SZ + col];
                    } else if (sbase < L) {
                        int src = L - 1 - sbase;
                        src = src < 0 ? 0 : (src > S_LEN - 1 ? S_LEN - 1 : src);
                        val = U[(size_t)src * D_SZ + col];
                    }
                }
                v_s[e] = val;
            }

            float4 pre;
            if (ldr) pre = ((const float4*)g_V0T)[tid];
            if (ldr) ((float4*)B_s)[tid] = pre;
            __syncthreads();

            u64 acc00 = 0, acc01 = 0, acc02 = 0, acc03 = 0;
            u64 acc10 = 0, acc11 = 0, acc12 = 0, acc13 = 0;

            for (int c = 0; c < NCHUNKS; c++) {
                const float* Bc = B_s + (c & 1) * CHELEMS;

                if (c + 1 < NCHUNKS && ldr)
                    pre = ((const float4*)(g_V0T + (size_t)(c + 1) * CHELEMS))[tid];

                if (tid < 128) {
                    const int meta = s_ck[c];
                    const int i  = meta >> 16;
                    const int j0 = meta & 0xffff;

                    const float vi0 = (i < TD) ? v_s[r0 * VS + i] : 1.0f;
                    const float vi1 = (i < TD) ? v_s[(r0 + 1) * VS + i] : 1.0f;
                    const ulonglong2* bp = (const ulonglong2*)Bc + tx * 2;

#pragma unroll
                    for (int kk = 0; kk < KC; kk++) {
                        float vj0 = v_s[r0 * VS + j0 + kk];
                        float vj1 = v_s[(r0 + 1) * VS + j0 + kk];
                        u64 a0 = dup2(vi0 * vj0);
                        u64 a1 = dup2(vi1 * vj1);
                        ulonglong2 b01 = bp[kk * 32];
                        ulonglong2 b23 = bp[kk * 32 + 1];
                        fma2(acc00, a0, b01.x); fma2(acc01, a0, b01.y);
                        fma2(acc02, a0, b23.x); fma2(acc03, a0, b23.y);
                        fma2(acc10, a1, b01.x); fma2(acc11, a1, b01.y);
                        fma2(acc12, a1, b23.x); fma2(acc13, a1, b23.y);
                    }
                }

                if (c + 1 < NCHUNKS && ldr)
                    ((float4*)(B_s + ((c + 1) & 1) * CHELEMS))[tid] = pre;
                __syncthreads();
            }

            if (tid < 128) {
                u64 accs[2][4] = {{acc00, acc01, acc02, acc03}, {acc10, acc11, acc12, acc13}};
#pragma unroll
                for (int rr = 0; rr < 2; rr++) {
#pragma unroll
                    for (int q = 0; q < 4; q++) {
                        float2 v2 = unpack2(accs[rr][q]);
                        int d = d0 + 2 * q;
                        if (d < D_SZ)     p_s[(r0 + rr) * D_SZ + d]     = sigf(v2.x + Wb[d]);
                        if (d + 1 < D_SZ) p_s[(r0 + rr) * D_SZ + d + 1] = sigf(v2.y + Wb[d + 1]);
                    }
                }
            }
            __syncthreads();

            for (int o = tid; o < MB * 400; o += NTHR) {
                int rl = o / 400;
                int g  = o % 400;
                float a = bih[g] + bhh[g];
                const float4* wr4 = (const float4*)(Wih + (size_t)g * D_SZ);
                const float4* pr4 = (const float4*)(p_s + rl * D_SZ);
#pragma unroll 5
                for (int q = 0; q < 25; q++) {
                    float4 w = wr4[q];
                    float4 p = pr4[q];
                    a = fmaf(w.x, p.x, a);
                    a = fmaf(w.y, p.y, a);
                    a = fmaf(w.z, p.z, a);
                    a = fmaf(w.w, p.w, a);
                }
                g_xg[(size_t)(row0 + rl) * 400 + g] = a;
            }

            float cw0 = convw[0], cw1 = convw[1], cw2 = convw[2], cw3 = convw[3], cw4 = convw[4];
            float cb = convb[0];
            for (int o = tid; o < MB * CO; o += NTHR) {
                int rl = o / CO;
                int oc = o % CO;
                const float* pr = p_s + rl * D_SZ;
                float s = cb;
                int base = 2 * oc - 4;
#pragma unroll
                for (int k = 0; k < 5; k++) {
                    int ix = base + k;
                    if (ix >= 0 && ix < D_SZ) {
                        float w = (k == 0) ? cw0 : (k == 1) ? cw1 : (k == 2) ? cw2 : (k == 3) ? cw3 : cw4;
                        s = fmaf(w, pr[ix], s);
                    }
                }
                g_h3[(size_t)(row0 + rl) * CO + oc] = s;
            }

            __syncthreads();
            __threadfence();
            if (tid == 0) atomicExch(&g_flag[tile], 1);
            __syncthreads();
        }
    } else {
        // ============ CONSUMER (LSTM): dim-grouped warps, ONE barrier/step ============
        // tid = d*8 + q*2 + half   (d=dim 0..99, q=gate type i/f/g/o, half=h-half)
        // All 4 gates of dim d live in one 8-lane group of one warp:
        //   acts exchanged with shfl.idx (no smem), c/h updated in lane sub==0.
        // h layout in smem (padded halves, 16B-aligned for LDS.128):
        //   half0: h[0..49] at float [0,50); half1: h[50..99] at float [52,102).
        float* xg_s = sm;                        // MB*400 = 6400 floats
        float* h_sc = sm + MB * 400;             // 104 floats (padded halves)

        const int d    = tid >> 3;               // 0..99
        const int sub  = tid & 7;
        const int q    = sub >> 1;               // gate type
        const int half = sub & 1;
        const int grow = q * 100 + d;            // gate row in Whh / g_xg

        // 25 u64 weights (50 regs) per thread — covers 50 of the 100 h dims.
        u64 w2[25];
        {
            const u64* wp = (const u64*)(Whh + (size_t)grow * D_SZ + half * 50);
#pragma unroll
            for (int j = 0; j < 25; j++) w2[j] = wp[j];
        }
        const uint32_t h_base = (uint32_t)__cvta_generic_to_shared(h_sc) + half * 208;
        // branchless activation params: g-gate uses tanh = 2*sig(2x)-1
        const float a_s   = (q == 2) ? 2.0f : 1.0f;   // input scale
        const float a_m   = (q == 2) ? 2.0f : 1.0f;   // output scale
        const float a_b   = (q == 2) ? -1.0f : 0.0f;  // output offset
        const int lane      = tid & 31;
        const int gbase     = lane & ~7;              // 8-group base lane

        float c = 0.0f;
        if (tid < 104) h_sc[tid] = 0.0f;
        __syncthreads();

        for (int tile = 0; tile < NTILES; tile++) {
            if (tid == 0) {
                while (atomicAdd(&g_flag[tile], 0) == 0) __nanosleep(64);
                __threadfence();
            }
            __syncthreads();

            // stage this tile's x_gates (6400 floats = 1600 float4)
            {
                const float4* src = (const float4*)(g_xg + (size_t)tile * MB * 400);
                float4* dst = (float4*)xg_s;
                dst[tid] = src[tid];
                dst[tid + NTHR] = src[tid + NTHR];
            }
            __syncthreads();

            for (int tt = 0; tt < MB; tt++) {
                const int t = tile * MB + tt;

                // half-dot over 50 h values
                u64 a0 = 0ull, a1 = 0ull, a2 = 0ull, a3 = 0ull;
                uint32_t addr = h_base;
#pragma unroll
                for (int b = 0; b < 6; b++) {
                    u64 h0, h1, h2, h3;
                    lds_v2u64(h0, h1, addr);
                    lds_v2u64(h2, h3, addr + 16);
                    fma2(a0, w2[4 * b],     h0);
                    fma2(a1, w2[4 * b + 1], h1);
                    fma2(a2, w2[4 * b + 2], h2);
                    fma2(a3, w2[4 * b + 3], h3);
                    addr += 32;
                }
                {
                    u64 ht;
                    lds_u64(ht, addr);
                    fma2(a0, w2[24], ht);
                }
                u64 st = add2(add2(a0, a1), add2(a2, a3));
                float2 uu = unpack2(st);
                float xh = uu.x + uu.y;
                xh += __shfl_xor_sync(0xffffffffu, xh, 1);
                float x = xh + xg_s[tt * 400 + grow];

                // activation (branchless): act = a_m * sig(a_s*x) + a_b
                float act = fmaf(a_m, sigf(a_s * x), a_b);

                // gather the 4 gate acts of this dim inside the warp
                float af = __shfl_sync(0xffffffffu, act, gbase + 2);
                float ag = __shfl_sync(0xffffffffu, act, gbase + 4);
                float ao = __shfl_sync(0xffffffffu, act, gbase + 6);

                if (sub == 0) {
                    // act == sigmoid(i); af=sig(f), ag=tanh(g), ao=sig(o)
                    c = fmaf(af, c, act * ag);
                    float h = ao * tanhfast(c);
                    int pos = d + (d >= 50 ? 2 : 0);
                    h_sc[pos] = h;
                    g_h[(size_t)t * D_SZ + d] = h;
                }
                __syncthreads();   // the ONE barrier: h visible for next step's dot
            }
        }
    }
}

// ---------------- K4: logits + log_softmax ----------------
__global__ void k4_epilogue(const float* __restrict__ Wsw, const float* __restrict__ Wsb,
                            float* __restrict__ out) {
    int t = blockIdx.x * blockDim.x + threadIdx.x;
    if (t >= S_LEN) return;
    const int L = g_L_dev[0];

    float acc[NC];
#pragma unroll
    for (int cc = 0; cc < NC; cc++) acc[cc] = Wsb[cc];

    const float* hf  = g_h  + (size_t)t * D_SZ;
    const float* h3f = g_h3 + (size_t)t * CO;

    for (int j = 0; j < D_SZ; j++) {
        float x = hf[j];
#pragma unroll
        for (int cc = 0; cc < NC; cc++) acc[cc] = fmaf(Wsw[cc * 304 + j], x, acc[cc]);
    }
    for (int j = 0; j < CO; j++) {
        float x = h3f[j];
#pragma unroll
        for (int cc = 0; cc < NC; cc++) acc[cc] = fmaf(Wsw[cc * 304 + 100 + j], x, acc[cc]);
    }

    if (t < L) {
        int sidx = L - 1 - t;
        sidx = sidx < 0 ? 0 : (sidx > S_LEN - 1 ? S_LEN - 1 : sidx);
        const float* hb  = g_h  + (size_t)(S_LEN + sidx) * D_SZ;
        const float* h3b = g_h3 + (size_t)(S_LEN + sidx) * CO;
        for (int j = 0; j < D_SZ; j++) {
            float x = hb[j];
#pragma unroll
            for (int cc = 0; cc < NC; cc++) acc[cc] = fmaf(Wsw[cc * 304 + 152 + j], x, acc[cc]);
        }
        for (int j = 0; j < CO; j++) {
            float x = h3b[j];
#pragma unroll
            for (int cc = 0; cc < NC; cc++) acc[cc] = fmaf(Wsw[cc * 304 + 252 + j], x, acc[cc]);
        }
    }

    float m = acc[0];
#pragma unroll
    for (int cc = 1; cc < NC; cc++) m = fmaxf(m, acc[cc]);
    float s = 0.0f;
#pragma unroll
    for (int cc = 0; cc < NC; cc++) s += __expf(acc[cc] - m);
    float lse = m + logf(s);
#pragma unroll
    for (int cc = 0; cc < NC; cc++) out[(size_t)t * NC + cc] = acc[cc] - lse;
}

// ---------------- launcher (single stream, fully serial-safe) ----------------
extern "C" void kernel_launch(void* const* d_in, const int* in_sizes, int n_in,
                              void* d_out, int out_size) {
    const float* U     = (const float*)d_in[0];
    const float* mask  = (const float*)d_in[1];
    const float* V     = (const float*)d_in[2];
    const float* Ww    = (const float*)d_in[3];
    const float* Wb    = (const float*)d_in[4];
    const float* Wsw   = (const float*)d_in[5];
    const float* Wsb   = (const float*)d_in[6];
    const float* Wih   = (const float*)d_in[7];
    const float* Whh   = (const float*)d_in[8];
    const float* bih   = (const float*)d_in[9];
    const float* bhh   = (const float*)d_in[10];
    const float* convw = (const float*)d_in[11];
    const float* convb = (const float*)d_in[12];
    float* out = (float*)d_out;

    const int smem2 = (MB * VS + 2 * CHELEMS + MB * D_SZ) * (int)sizeof(float)
                    + NCHUNKS * (int)sizeof(int);   // ~45.7 KB (covers consumer's 26 KB too)

    static bool attr_set = false;
    if (!attr_set) {
        cudaFuncSetAttribute(k23_fused, cudaFuncAttributeMaxDynamicSharedMemorySize, smem2);
        attr_set = true;
    }

    k_init<<<1, 32>>>();
    k0_fill<<<2048, 256>>>(V, Ww);
    k1_len<<<1, 1024>>>(mask, in_sizes[1]);
    k23_fused<<<NPROD + 1, NTHR, smem2>>>(U, Wb, Wih, bih, bhh, convw, convb, Whh);
    k4_epilogue<<<32, 128>>>(Wsw, Wsb, out);
}